// round 2
// baseline (speedup 1.0000x reference)
#include <cuda_runtime.h>
#include <math.h>

#define B_    256
#define T_    64
#define MROWS (B_*T_)      // 16384
#define KDIM  753          // F layout: [xemb(32), treat(1), gemb(720)]
#define NDIM  640          // [a_pre(128), o_pre(128), gi(384)]
#define HID_  128

// ---- scratch (static device globals; no runtime allocation allowed) ----
__device__ float g_F[(size_t)MROWS * KDIM];     // ~49 MB feature matrix
__device__ float g_W[(size_t)KDIM * NDIM];      // ~1.9 MB fused weight
__device__ float g_O[(size_t)MROWS * NDIM];     // ~42 MB GEMM output
__device__ float g_da[B_ * HID_];               // b_a1 + demo @ W_a1[:, :10]^T
__device__ float g_do[B_ * HID_];               // b_o1 + demo @ W_o1[:, 32:42]^T

__device__ __forceinline__ float eluf(float x) { return x > 0.f ? x : expm1f(x); }

// ============================================================
// Build fused weight matrix g_W (KDIM x NDIM, row-major)
// cols [0,128): W_a1 gemb part (zero for xemb/treat rows)
// cols [128,256): W_o1 remapped to F layout
// cols [256,640): W_ih (rnn_in layout == F layout)
// ============================================================
__global__ void build_w(const float* __restrict__ W_a1,
                        const float* __restrict__ W_o1,
                        const float* __restrict__ W_ih) {
    int idx = blockIdx.x * 256 + threadIdx.x;
    if (idx >= KDIM * NDIM) return;
    int k = idx / NDIM, c = idx % NDIM;
    float v;
    if (c < 128) {
        v = (k < 33) ? 0.f : W_a1[c * 730 + 10 + (k - 33)];
    } else if (c < 256) {
        int co = c - 128;
        if (k < 32)       v = W_o1[co * 763 + k];
        else if (k == 32) v = W_o1[co * 763 + 42];
        else              v = W_o1[co * 763 + 43 + (k - 33)];
    } else {
        v = W_ih[(c - 256) * 753 + k];
    }
    g_W[idx] = v;
}

// ============================================================
// Per-batch demo precompute (time-invariant part of a_pre / o_pre)
// ============================================================
__global__ void demo_k(const float* __restrict__ x_demo,
                       const float* __restrict__ W_stat, const float* __restrict__ b_stat,
                       const float* __restrict__ W_a1,   const float* __restrict__ b_a1,
                       const float* __restrict__ W_o1,   const float* __restrict__ b_o1) {
    int b = blockIdx.x;
    int tid = threadIdx.x;  // 128
    __shared__ float d_sh[10];
    if (tid < 10) {
        float s = b_stat[tid];
        #pragma unroll
        for (int q = 0; q < 10; q++) s += x_demo[b * 10 + q] * W_stat[tid * 10 + q];
        d_sh[tid] = s;
    }
    __syncthreads();
    float sa = b_a1[tid], so = b_o1[tid];
    #pragma unroll
    for (int s = 0; s < 10; s++) {
        sa += d_sh[s] * W_a1[tid * 730 + s];
        so += d_sh[s] * W_o1[tid * 763 + 32 + s];
    }
    g_da[b * HID_ + tid] = sa;
    g_do[b * HID_ + tid] = so;
}

// ============================================================
// Feature kernel: per (b,t) build F row = [xemb, treat, gemb]
// 1 block (128 threads) per position: agents/xemb phase 1, edges phase 2
// ============================================================
__global__ void __launch_bounds__(128) feat_k(
    const float* __restrict__ x, const float* __restrict__ f_treat,
    const float* __restrict__ W_x2emb, const float* __restrict__ b_x2emb,
    const float* __restrict__ W_m1a, const float* __restrict__ b_m1a,
    const float* __restrict__ W_m1b, const float* __restrict__ b_m1b,
    const float* __restrict__ W_m2a, const float* __restrict__ b_m2a,
    const float* __restrict__ W_m2b, const float* __restrict__ b_m2b) {
    int m = blockIdx.x;
    int b = m >> 6, t = m & 63;
    int tid = threadIdx.x;

    __shared__ float h1s[80];
    __shared__ float w1a[32], w1b[64], w2a[128], w2b[64], wx[128];
    __shared__ float bx[32], bw1a[8], bw1b[8], bw2a[8], bw2b[8];

    // preload small weights
    w2a[tid] = W_m2a[tid];
    wx[tid]  = W_x2emb[tid];
    if (tid < 64) { w1b[tid] = W_m1b[tid]; w2b[tid] = W_m2b[tid]; }
    if (tid < 32) { w1a[tid] = W_m1a[tid]; bx[tid] = b_x2emb[tid]; }
    if (tid < 8)  { bw1a[tid] = b_m1a[tid]; bw1b[tid] = b_m1b[tid];
                    bw2a[tid] = b_m2a[tid]; bw2b[tid] = b_m2b[tid]; }
    __syncthreads();

    const float* xr = x + ((size_t)b * 65 + t) * 44;
    float* Frow = g_F + (size_t)m * KDIM;

    if (tid < 10) {
        // agent MLP: 4 -> 8 -> 8
        float xa[4];
        #pragma unroll
        for (int q = 0; q < 4; q++) xa[q] = xr[tid * 4 + q];
        float l1[8];
        #pragma unroll
        for (int j = 0; j < 8; j++) {
            float s = bw1a[j];
            #pragma unroll
            for (int q = 0; q < 4; q++) s += w1a[j * 4 + q] * xa[q];
            l1[j] = eluf(s);
        }
        #pragma unroll
        for (int j = 0; j < 8; j++) {
            float s = bw1b[j];
            #pragma unroll
            for (int q = 0; q < 8; q++) s += w1b[j * 8 + q] * l1[q];
            h1s[tid * 8 + j] = eluf(s);
        }
    } else if (tid >= 96) {
        int jj = tid - 96;  // xemb output 0..31
        float s = bx[jj];
        #pragma unroll
        for (int q = 0; q < 4; q++) s += wx[jj * 4 + q] * xr[40 + q];
        Frow[jj] = s;
    } else if (tid == 95) {
        Frow[32] = f_treat[(size_t)b * 65 + t];
    }
    __syncthreads();

    if (tid < 90) {
        // edge MLP: 16 -> 8 -> 8
        int e = tid;
        int i = e / 9, r = e % 9;
        int jn = (r < i) ? r : r + 1;
        float f[16];
        #pragma unroll
        for (int q = 0; q < 8; q++) { f[q] = h1s[i * 8 + q]; f[8 + q] = h1s[jn * 8 + q]; }
        float l1[8];
        #pragma unroll
        for (int j = 0; j < 8; j++) {
            float s = bw2a[j];
            #pragma unroll
            for (int q = 0; q < 16; q++) s += w2a[j * 16 + q] * f[q];
            l1[j] = eluf(s);
        }
        #pragma unroll
        for (int j = 0; j < 8; j++) {
            float s = bw2b[j];
            #pragma unroll
            for (int q = 0; q < 8; q++) s += w2b[j * 8 + q] * l1[q];
            Frow[33 + e * 8 + j] = eluf(s);
        }
    }
}

// ============================================================
// Fused SGEMM: g_O (16384 x 640) = g_F (16384 x 753) @ g_W (753 x 640)
// 128x64 tile, BK=16, 256 threads, 8x4 register tile
// ============================================================
#define BM 128
#define BN 64
#define BK 16
__global__ void __launch_bounds__(256) sgemm() {
    __shared__ float As[BK][BM];
    __shared__ float Bs[BK][BN];
    const int bm = blockIdx.y * BM, bn = blockIdx.x * BN;
    const int tid = threadIdx.x;
    const int tx = tid & 15, ty = tid >> 4;

    float acc[8][4];
    #pragma unroll
    for (int i = 0; i < 8; i++)
        #pragma unroll
        for (int j = 0; j < 4; j++) acc[i][j] = 0.f;

    for (int k0 = 0; k0 < KDIM; k0 += BK) {
        #pragma unroll
        for (int p = 0; p < 8; p++) {
            int i = tid + p * 256;
            int k = i & 15, ml = i >> 4;
            int kg = k0 + k;
            As[k][ml] = (kg < KDIM) ? g_F[(size_t)(bm + ml) * KDIM + kg] : 0.f;
        }
        #pragma unroll
        for (int p = 0; p < 4; p++) {
            int i = tid + p * 256;
            int n = i & 63, k = i >> 6;
            int kg = k0 + k;
            Bs[k][n] = (kg < KDIM) ? g_W[(size_t)kg * NDIM + bn + n] : 0.f;
        }
        __syncthreads();
        #pragma unroll
        for (int kk = 0; kk < BK; kk++) {
            float4 b0 = *(const float4*)&Bs[kk][tx * 4];
            float4 a0 = *(const float4*)&As[kk][ty * 8];
            float4 a1 = *(const float4*)&As[kk][ty * 8 + 4];
            float av[8] = {a0.x, a0.y, a0.z, a0.w, a1.x, a1.y, a1.z, a1.w};
            float bv[4] = {b0.x, b0.y, b0.z, b0.w};
            #pragma unroll
            for (int i = 0; i < 8; i++)
                #pragma unroll
                for (int j = 0; j < 4; j++)
                    acc[i][j] += av[i] * bv[j];
        }
        __syncthreads();
    }
    #pragma unroll
    for (int i = 0; i < 8; i++) {
        float4 v = make_float4(acc[i][0], acc[i][1], acc[i][2], acc[i][3]);
        *(float4*)&g_O[(size_t)(bm + ty * 8 + i) * NDIM + bn + tx * 4] = v;
    }
}

// ============================================================
// Head kernel: a_out / y_out (128 -> 1 with relu), warp per row
// ============================================================
__global__ void head_k(const float* __restrict__ W_a2, const float* __restrict__ W_o2,
                       float* __restrict__ out) {
    int m = blockIdx.x * 8 + threadIdx.y;
    int lane = threadIdx.x;
    int b = m >> 6;
    const float* row = g_O + (size_t)m * NDIM;
    float sa = 0.f, so = 0.f;
    #pragma unroll
    for (int q = 0; q < 4; q++) {
        int c = lane * 4 + q;
        float av = row[c] + g_da[b * HID_ + c];
        sa += fmaxf(av, 0.f) * W_a2[c];
        float ov = row[128 + c] + g_do[b * HID_ + c];
        so += fmaxf(ov, 0.f) * W_o2[c];
    }
    #pragma unroll
    for (int off = 16; off; off >>= 1) {
        sa += __shfl_down_sync(0xffffffffu, sa, off);
        so += __shfl_down_sync(0xffffffffu, so, off);
    }
    if (lane == 0) {
        out[(size_t)m * 130 + 0] = sa;
        out[(size_t)m * 130 + 1] = so;
    }
}

// ============================================================
// GRU scan: 1 block per batch sample, 384 threads.
// Thread j holds W_hh row j in registers; h in shared.
// ============================================================
__global__ void __launch_bounds__(384, 1) gru_k(
    const float* __restrict__ h0, const float* __restrict__ W_hh,
    const float* __restrict__ b_hh, const float* __restrict__ b_ih,
    float* __restrict__ out) {
    int b = blockIdx.x;
    int j = threadIdx.x;

    __shared__ float h_sh[128];
    __shared__ float gh_sh[384];
    __shared__ float bih_sh[384];

    float4 w[32];
    #pragma unroll
    for (int q = 0; q < 32; q++) w[q] = *(const float4*)&W_hh[(size_t)j * 128 + q * 4];
    float bh = b_hh[j];
    bih_sh[j] = b_ih[j];
    if (j < 128) h_sh[j] = h0[b * 128 + j];
    __syncthreads();

    for (int t = 0; t < T_; t++) {
        int m = b * T_ + t;
        float acc = bh;
        const float4* hv4 = (const float4*)h_sh;
        #pragma unroll
        for (int q = 0; q < 32; q++) {
            float4 hv = hv4[q];
            acc += w[q].x * hv.x + w[q].y * hv.y + w[q].z * hv.z + w[q].w * hv.w;
        }
        gh_sh[j] = acc;
        __syncthreads();
        if (j < 128) {
            const float* gim = g_O + (size_t)m * NDIM + 256;
            float i_r = gim[j]       + bih_sh[j];
            float i_z = gim[128 + j] + bih_sh[128 + j];
            float i_n = gim[256 + j] + bih_sh[256 + j];
            float hr = gh_sh[j], hz = gh_sh[128 + j], hn = gh_sh[256 + j];
            float r = 1.f / (1.f + expf(-(i_r + hr)));
            float z = 1.f / (1.f + expf(-(i_z + hz)));
            float n = tanhf(i_n + r * hn);
            float h_new = (1.f - z) * n + z * h_sh[j];
            h_sh[j] = h_new;
            out[(size_t)m * 130 + 2 + j] = h_new;
        }
        __syncthreads();
    }
}

// ============================================================
extern "C" void kernel_launch(void* const* d_in, const int* in_sizes, int n_in,
                              void* d_out, int out_size) {
    const float* x        = (const float*)d_in[0];
    const float* x_demo   = (const float*)d_in[1];
    const float* f_treat  = (const float*)d_in[2];
    const float* h0       = (const float*)d_in[3];
    const float* W_x2emb  = (const float*)d_in[4];
    const float* b_x2emb  = (const float*)d_in[5];
    const float* W_stat   = (const float*)d_in[6];
    const float* b_stat   = (const float*)d_in[7];
    const float* W_m1a    = (const float*)d_in[8];
    const float* b_m1a    = (const float*)d_in[9];
    const float* W_m1b    = (const float*)d_in[10];
    const float* b_m1b    = (const float*)d_in[11];
    const float* W_m2a    = (const float*)d_in[12];
    const float* b_m2a    = (const float*)d_in[13];
    const float* W_m2b    = (const float*)d_in[14];
    const float* b_m2b    = (const float*)d_in[15];
    const float* W_a1     = (const float*)d_in[16];
    const float* b_a1     = (const float*)d_in[17];
    const float* W_a2     = (const float*)d_in[18];
    const float* W_o1     = (const float*)d_in[19];
    const float* b_o1     = (const float*)d_in[20];
    const float* W_o2     = (const float*)d_in[21];
    const float* W_ih     = (const float*)d_in[22];
    const float* b_ih     = (const float*)d_in[23];
    const float* W_hh     = (const float*)d_in[24];
    const float* b_hh     = (const float*)d_in[25];
    float* out = (float*)d_out;

    build_w<<<(KDIM * NDIM + 255) / 256, 256>>>(W_a1, W_o1, W_ih);
    demo_k<<<B_, 128>>>(x_demo, W_stat, b_stat, W_a1, b_a1, W_o1, b_o1);
    feat_k<<<MROWS, 128>>>(x, f_treat, W_x2emb, b_x2emb,
                           W_m1a, b_m1a, W_m1b, b_m1b,
                           W_m2a, b_m2a, W_m2b, b_m2b);
    dim3 gg(NDIM / BN, MROWS / BM);
    sgemm<<<gg, 256>>>();
    head_k<<<MROWS / 8, dim3(32, 8)>>>(W_a2, W_o2, out);
    gru_k<<<B_, 384>>>(h0, W_hh, b_hh, b_ih, out);
}

// round 3
// speedup vs baseline: 1.5883x; 1.5883x over previous
#include <cuda_runtime.h>
#include <math.h>
#include <stdint.h>

#define B_    256
#define T_    64
#define MROWS (B_*T_)      // 16384
#define KDIM  753          // F layout: [xemb(32), treat(1), gemb(720)]
#define KPAD  768          // padded K (zeros in [753,768))
#define NDIM  640          // [a_pre(128), o_pre(128), gi(384)]
#define HID_  128

// ---- scratch (static device globals; no runtime allocation allowed) ----
__device__ float g_F[(size_t)MROWS * KPAD];     // ~50 MB feature matrix (padded)
__device__ float g_W[(size_t)KPAD * NDIM];      // ~2 MB fused weight (padded)
__device__ float g_O[(size_t)MROWS * NDIM];     // ~42 MB GEMM output
__device__ float g_da[B_ * HID_];               // b_a1 + demo @ W_a1[:, :10]^T
__device__ float g_do[B_ * HID_];               // b_o1 + demo @ W_o1[:, 32:42]^T

__device__ __forceinline__ float eluf(float x) { return x > 0.f ? x : expm1f(x); }

__device__ __forceinline__ uint32_t f2tf32(float x) {
    uint32_t r; asm("cvt.rna.tf32.f32 %0, %1;" : "=r"(r) : "f"(x)); return r;
}

__device__ __forceinline__ void mma_tf32(float* c, const uint32_t* a, const uint32_t* b) {
    asm volatile(
        "mma.sync.aligned.m16n8k8.row.col.f32.tf32.tf32.f32 "
        "{%0,%1,%2,%3}, {%4,%5,%6,%7}, {%8,%9}, {%0,%1,%2,%3};"
        : "+f"(c[0]), "+f"(c[1]), "+f"(c[2]), "+f"(c[3])
        : "r"(a[0]), "r"(a[1]), "r"(a[2]), "r"(a[3]), "r"(b[0]), "r"(b[1]));
}

// ============================================================
// Build fused weight matrix g_W (KPAD x NDIM, row-major), zero pad rows
// ============================================================
__global__ void build_w(const float* __restrict__ W_a1,
                        const float* __restrict__ W_o1,
                        const float* __restrict__ W_ih) {
    int idx = blockIdx.x * 256 + threadIdx.x;
    if (idx >= KPAD * NDIM) return;
    int k = idx / NDIM, c = idx % NDIM;
    float v;
    if (k >= KDIM) {
        v = 0.f;
    } else if (c < 128) {
        v = (k < 33) ? 0.f : W_a1[c * 730 + 10 + (k - 33)];
    } else if (c < 256) {
        int co = c - 128;
        if (k < 32)       v = W_o1[co * 763 + k];
        else if (k == 32) v = W_o1[co * 763 + 42];
        else              v = W_o1[co * 763 + 43 + (k - 33)];
    } else {
        v = W_ih[(c - 256) * 753 + k];
    }
    g_W[idx] = v;
}

// ============================================================
// Per-batch demo precompute (time-invariant part of a_pre / o_pre)
// ============================================================
__global__ void demo_k(const float* __restrict__ x_demo,
                       const float* __restrict__ W_stat, const float* __restrict__ b_stat,
                       const float* __restrict__ W_a1,   const float* __restrict__ b_a1,
                       const float* __restrict__ W_o1,   const float* __restrict__ b_o1) {
    int b = blockIdx.x;
    int tid = threadIdx.x;  // 128
    __shared__ float d_sh[10];
    if (tid < 10) {
        float s = b_stat[tid];
        #pragma unroll
        for (int q = 0; q < 10; q++) s += x_demo[b * 10 + q] * W_stat[tid * 10 + q];
        d_sh[tid] = s;
    }
    __syncthreads();
    float sa = b_a1[tid], so = b_o1[tid];
    #pragma unroll
    for (int s = 0; s < 10; s++) {
        sa += d_sh[s] * W_a1[tid * 730 + s];
        so += d_sh[s] * W_o1[tid * 763 + 32 + s];
    }
    g_da[b * HID_ + tid] = sa;
    g_do[b * HID_ + tid] = so;
}

// ============================================================
// Feature kernel: per (b,t) build F row = [xemb, treat, gemb, pad0]
// ============================================================
__global__ void __launch_bounds__(128) feat_k(
    const float* __restrict__ x, const float* __restrict__ f_treat,
    const float* __restrict__ W_x2emb, const float* __restrict__ b_x2emb,
    const float* __restrict__ W_m1a, const float* __restrict__ b_m1a,
    const float* __restrict__ W_m1b, const float* __restrict__ b_m1b,
    const float* __restrict__ W_m2a, const float* __restrict__ b_m2a,
    const float* __restrict__ W_m2b, const float* __restrict__ b_m2b) {
    int m = blockIdx.x;
    int b = m >> 6, t = m & 63;
    int tid = threadIdx.x;

    __shared__ float h1s[80];
    __shared__ float w1a[32], w1b[64], w2a[128], w2b[64], wx[128];
    __shared__ float bx[32], bw1a[8], bw1b[8], bw2a[8], bw2b[8];

    w2a[tid] = W_m2a[tid];
    wx[tid]  = W_x2emb[tid];
    if (tid < 64) { w1b[tid] = W_m1b[tid]; w2b[tid] = W_m2b[tid]; }
    if (tid < 32) { w1a[tid] = W_m1a[tid]; bx[tid] = b_x2emb[tid]; }
    if (tid < 8)  { bw1a[tid] = b_m1a[tid]; bw1b[tid] = b_m1b[tid];
                    bw2a[tid] = b_m2a[tid]; bw2b[tid] = b_m2b[tid]; }
    __syncthreads();

    const float* xr = x + ((size_t)b * 65 + t) * 44;
    float* Frow = g_F + (size_t)m * KPAD;

    if (tid < 10) {
        float xa[4];
        #pragma unroll
        for (int q = 0; q < 4; q++) xa[q] = xr[tid * 4 + q];
        float l1[8];
        #pragma unroll
        for (int j = 0; j < 8; j++) {
            float s = bw1a[j];
            #pragma unroll
            for (int q = 0; q < 4; q++) s += w1a[j * 4 + q] * xa[q];
            l1[j] = eluf(s);
        }
        #pragma unroll
        for (int j = 0; j < 8; j++) {
            float s = bw1b[j];
            #pragma unroll
            for (int q = 0; q < 8; q++) s += w1b[j * 8 + q] * l1[q];
            h1s[tid * 8 + j] = eluf(s);
        }
    } else if (tid >= 96) {
        int jj = tid - 96;
        float s = bx[jj];
        #pragma unroll
        for (int q = 0; q < 4; q++) s += wx[jj * 4 + q] * xr[40 + q];
        Frow[jj] = s;
    } else if (tid == 95) {
        Frow[32] = f_treat[(size_t)b * 65 + t];
    } else if (tid >= 80 && tid < 95) {
        Frow[KDIM + (tid - 80)] = 0.f;   // zero the K pad [753,768)
    }
    __syncthreads();

    if (tid < 90) {
        int e = tid;
        int i = e / 9, r = e % 9;
        int jn = (r < i) ? r : r + 1;
        float f[16];
        #pragma unroll
        for (int q = 0; q < 8; q++) { f[q] = h1s[i * 8 + q]; f[8 + q] = h1s[jn * 8 + q]; }
        float l1[8];
        #pragma unroll
        for (int j = 0; j < 8; j++) {
            float s = bw2a[j];
            #pragma unroll
            for (int q = 0; q < 16; q++) s += w2a[j * 16 + q] * f[q];
            l1[j] = eluf(s);
        }
        #pragma unroll
        for (int j = 0; j < 8; j++) {
            float s = bw2b[j];
            #pragma unroll
            for (int q = 0; q < 8; q++) s += w2b[j * 8 + q] * l1[q];
            Frow[33 + e * 8 + j] = eluf(s);
        }
    }
}

// ============================================================
// 3xTF32 tensor-core GEMM:
// g_O (16384 x 640) = g_F (16384 x 768) @ g_W (768 x 640)
// Block: 128 threads (4 warps, 2x2), tile 128x64, BK=16.
// Warp tile 64x32 = 4x4 grid of m16n8k8 mma, 3 passes (hi*hi, hi*lo, lo*hi).
// smem strides chosen ≡ 8 (mod 32) so fragment k-rows hit disjoint banks.
// ============================================================
#define GBM 128
#define GBN 64
#define GBK 16
#define ASTR (GBM + 8)   // 136 ≡ 8 mod 32
#define BSTR (GBN + 8)   // 72  ≡ 8 mod 32

__global__ void __launch_bounds__(128) gemm_tf32() {
    __shared__ float Ah[GBK][ASTR], Al[GBK][ASTR];
    __shared__ float Bh[GBK][BSTR], Bl[GBK][BSTR];

    const int tid  = threadIdx.x;
    const int warp = tid >> 5, lane = tid & 31;
    const int g = lane >> 2, tg = lane & 3;
    const int wm = (warp & 1) * 64;   // warp M offset in tile
    const int wn = (warp >> 1) * 32;  // warp N offset in tile
    const int bm = blockIdx.y * GBM, bn = blockIdx.x * GBN;

    float acc[4][4][4];
    #pragma unroll
    for (int i = 0; i < 4; i++)
        #pragma unroll
        for (int j = 0; j < 4; j++)
            #pragma unroll
            for (int q = 0; q < 4; q++) acc[i][j][q] = 0.f;

    const float* Abase = g_F + (size_t)(bm + tid) * KPAD;
    const int brow = tid >> 4;            // 0..7
    const int bcol = (tid & 15) * 4;      // 0..60

    for (int k0 = 0; k0 < KPAD; k0 += GBK) {
        // --- load A tile: thread = one row (m=tid), 16 consecutive k ---
        #pragma unroll
        for (int q = 0; q < 4; q++) {
            float4 v = *(const float4*)(Abase + k0 + q * 4);
            float f[4] = {v.x, v.y, v.z, v.w};
            #pragma unroll
            for (int e = 0; e < 4; e++) {
                float hi = __uint_as_float(f2tf32(f[e]));
                Ah[q * 4 + e][tid] = hi;
                Al[q * 4 + e][tid] = __uint_as_float(f2tf32(f[e] - hi));
            }
        }
        // --- load B tile: 16x64, two passes of 8 rows ---
        #pragma unroll
        for (int p = 0; p < 2; p++) {
            int kr = brow + p * 8;
            float4 v = *(const float4*)(g_W + (size_t)(k0 + kr) * NDIM + bn + bcol);
            float f[4] = {v.x, v.y, v.z, v.w};
            float hi[4], lo[4];
            #pragma unroll
            for (int e = 0; e < 4; e++) {
                hi[e] = __uint_as_float(f2tf32(f[e]));
                lo[e] = __uint_as_float(f2tf32(f[e] - hi[e]));
            }
            *(float4*)&Bh[kr][bcol] = make_float4(hi[0], hi[1], hi[2], hi[3]);
            *(float4*)&Bl[kr][bcol] = make_float4(lo[0], lo[1], lo[2], lo[3]);
        }
        __syncthreads();

        #pragma unroll
        for (int ks = 0; ks < 2; ks++) {
            const int kb = ks * 8;
            uint32_t a_h[4][4], a_l[4][4], b_h[4][2], b_l[4][2];
            #pragma unroll
            for (int mt = 0; mt < 4; mt++) {
                int mr = wm + mt * 16 + g;
                a_h[mt][0] = __float_as_uint(Ah[kb + tg][mr]);
                a_h[mt][1] = __float_as_uint(Ah[kb + tg][mr + 8]);
                a_h[mt][2] = __float_as_uint(Ah[kb + tg + 4][mr]);
                a_h[mt][3] = __float_as_uint(Ah[kb + tg + 4][mr + 8]);
                a_l[mt][0] = __float_as_uint(Al[kb + tg][mr]);
                a_l[mt][1] = __float_as_uint(Al[kb + tg][mr + 8]);
                a_l[mt][2] = __float_as_uint(Al[kb + tg + 4][mr]);
                a_l[mt][3] = __float_as_uint(Al[kb + tg + 4][mr + 8]);
            }
            #pragma unroll
            for (int nt = 0; nt < 4; nt++) {
                int nc = wn + nt * 8 + g;
                b_h[nt][0] = __float_as_uint(Bh[kb + tg][nc]);
                b_h[nt][1] = __float_as_uint(Bh[kb + tg + 4][nc]);
                b_l[nt][0] = __float_as_uint(Bl[kb + tg][nc]);
                b_l[nt][1] = __float_as_uint(Bl[kb + tg + 4][nc]);
            }
            #pragma unroll
            for (int mt = 0; mt < 4; mt++)
                #pragma unroll
                for (int nt = 0; nt < 4; nt++) {
                    mma_tf32(acc[mt][nt], a_h[mt], b_h[nt]);
                    mma_tf32(acc[mt][nt], a_h[mt], b_l[nt]);
                    mma_tf32(acc[mt][nt], a_l[mt], b_h[nt]);
                }
        }
        __syncthreads();
    }

    // epilogue
    #pragma unroll
    for (int mt = 0; mt < 4; mt++) {
        #pragma unroll
        for (int nt = 0; nt < 4; nt++) {
            int row = bm + wm + mt * 16 + g;
            int col = bn + wn + nt * 8 + tg * 2;
            *(float2*)&g_O[(size_t)row * NDIM + col] =
                make_float2(acc[mt][nt][0], acc[mt][nt][1]);
            *(float2*)&g_O[(size_t)(row + 8) * NDIM + col] =
                make_float2(acc[mt][nt][2], acc[mt][nt][3]);
        }
    }
}

// ============================================================
// Head kernel: a_out / y_out (128 -> 1 with relu), warp per row
// ============================================================
__global__ void head_k(const float* __restrict__ W_a2, const float* __restrict__ W_o2,
                       float* __restrict__ out) {
    int m = blockIdx.x * 8 + threadIdx.y;
    int lane = threadIdx.x;
    int b = m >> 6;
    const float* row = g_O + (size_t)m * NDIM;
    float sa = 0.f, so = 0.f;
    #pragma unroll
    for (int q = 0; q < 4; q++) {
        int c = lane * 4 + q;
        float av = row[c] + g_da[b * HID_ + c];
        sa += fmaxf(av, 0.f) * W_a2[c];
        float ov = row[128 + c] + g_do[b * HID_ + c];
        so += fmaxf(ov, 0.f) * W_o2[c];
    }
    #pragma unroll
    for (int off = 16; off; off >>= 1) {
        sa += __shfl_down_sync(0xffffffffu, sa, off);
        so += __shfl_down_sync(0xffffffffu, so, off);
    }
    if (lane == 0) {
        out[(size_t)m * 130 + 0] = sa;
        out[(size_t)m * 130 + 1] = so;
    }
}

// ============================================================
// GRU scan: 1 block per batch sample, 384 threads.
// ============================================================
__global__ void __launch_bounds__(384, 1) gru_k(
    const float* __restrict__ h0, const float* __restrict__ W_hh,
    const float* __restrict__ b_hh, const float* __restrict__ b_ih,
    float* __restrict__ out) {
    int b = blockIdx.x;
    int j = threadIdx.x;

    __shared__ float h_sh[128];
    __shared__ float gh_sh[384];
    __shared__ float bih_sh[384];

    float4 w[32];
    #pragma unroll
    for (int q = 0; q < 32; q++) w[q] = *(const float4*)&W_hh[(size_t)j * 128 + q * 4];
    float bh = b_hh[j];
    bih_sh[j] = b_ih[j];
    if (j < 128) h_sh[j] = h0[b * 128 + j];
    __syncthreads();

    for (int t = 0; t < T_; t++) {
        int m = b * T_ + t;
        float acc = bh;
        const float4* hv4 = (const float4*)h_sh;
        #pragma unroll
        for (int q = 0; q < 32; q++) {
            float4 hv = hv4[q];
            acc += w[q].x * hv.x + w[q].y * hv.y + w[q].z * hv.z + w[q].w * hv.w;
        }
        gh_sh[j] = acc;
        __syncthreads();
        if (j < 128) {
            const float* gim = g_O + (size_t)m * NDIM + 256;
            float i_r = gim[j]       + bih_sh[j];
            float i_z = gim[128 + j] + bih_sh[128 + j];
            float i_n = gim[256 + j] + bih_sh[256 + j];
            float hr = gh_sh[j], hz = gh_sh[128 + j], hn = gh_sh[256 + j];
            float r = 1.f / (1.f + expf(-(i_r + hr)));
            float z = 1.f / (1.f + expf(-(i_z + hz)));
            float n = tanhf(i_n + r * hn);
            float h_new = (1.f - z) * n + z * h_sh[j];
            h_sh[j] = h_new;
            out[(size_t)m * 130 + 2 + j] = h_new;
        }
        __syncthreads();
    }
}

// ============================================================
extern "C" void kernel_launch(void* const* d_in, const int* in_sizes, int n_in,
                              void* d_out, int out_size) {
    const float* x        = (const float*)d_in[0];
    const float* x_demo   = (const float*)d_in[1];
    const float* f_treat  = (const float*)d_in[2];
    const float* h0       = (const float*)d_in[3];
    const float* W_x2emb  = (const float*)d_in[4];
    const float* b_x2emb  = (const float*)d_in[5];
    const float* W_stat   = (const float*)d_in[6];
    const float* b_stat   = (const float*)d_in[7];
    const float* W_m1a    = (const float*)d_in[8];
    const float* b_m1a    = (const float*)d_in[9];
    const float* W_m1b    = (const float*)d_in[10];
    const float* b_m1b    = (const float*)d_in[11];
    const float* W_m2a    = (const float*)d_in[12];
    const float* b_m2a    = (const float*)d_in[13];
    const float* W_m2b    = (const float*)d_in[14];
    const float* b_m2b    = (const float*)d_in[15];
    const float* W_a1     = (const float*)d_in[16];
    const float* b_a1     = (const float*)d_in[17];
    const float* W_a2     = (const float*)d_in[18];
    const float* W_o1     = (const float*)d_in[19];
    const float* b_o1     = (const float*)d_in[20];
    const float* W_o2     = (const float*)d_in[21];
    const float* W_ih     = (const float*)d_in[22];
    const float* b_ih     = (const float*)d_in[23];
    const float* W_hh     = (const float*)d_in[24];
    const float* b_hh     = (const float*)d_in[25];
    float* out = (float*)d_out;

    build_w<<<(KPAD * NDIM + 255) / 256, 256>>>(W_a1, W_o1, W_ih);
    demo_k<<<B_, 128>>>(x_demo, W_stat, b_stat, W_a1, b_a1, W_o1, b_o1);
    feat_k<<<MROWS, 128>>>(x, f_treat, W_x2emb, b_x2emb,
                           W_m1a, b_m1a, W_m1b, b_m1b,
                           W_m2a, b_m2a, W_m2b, b_m2b);
    dim3 gg(NDIM / GBN, MROWS / GBM);
    gemm_tf32<<<gg, 128>>>();
    head_k<<<MROWS / 8, dim3(32, 8)>>>(W_a2, W_o2, out);
    gru_k<<<B_, 384>>>(h0, W_hh, b_hh, b_ih, out);
}

// round 4
// speedup vs baseline: 1.8294x; 1.1519x over previous
#include <cuda_runtime.h>
#include <math.h>
#include <stdint.h>

#define B_    256
#define T_    64
#define MROWS (B_*T_)      // 16384
#define KDIM  753          // F layout: [xemb(32), treat(1), gemb(720)]
#define KPAD  768          // padded K (zeros in [753,768))
#define NDIM  640          // [a_pre(128), o_pre(128), gi(384)]
#define HID_  128

// ---- scratch (static device globals; no runtime allocation allowed) ----
__device__ float g_F[(size_t)MROWS * KPAD];
__device__ float g_W[(size_t)KPAD * NDIM];
__device__ float g_O[(size_t)MROWS * NDIM];
__device__ float g_da[B_ * HID_];
__device__ float g_do[B_ * HID_];

__device__ __forceinline__ float eluf(float x) { return x > 0.f ? x : expm1f(x); }

__device__ __forceinline__ uint32_t f2tf32(float x) {
    uint32_t r; asm("cvt.rna.tf32.f32 %0, %1;" : "=r"(r) : "f"(x)); return r;
}

__device__ __forceinline__ void mma_tf32(float* c, const uint32_t* a, const uint32_t* b) {
    asm volatile(
        "mma.sync.aligned.m16n8k8.row.col.f32.tf32.tf32.f32 "
        "{%0,%1,%2,%3}, {%4,%5,%6,%7}, {%8,%9}, {%0,%1,%2,%3};"
        : "+f"(c[0]), "+f"(c[1]), "+f"(c[2]), "+f"(c[3])
        : "r"(a[0]), "r"(a[1]), "r"(a[2]), "r"(a[3]), "r"(b[0]), "r"(b[1]));
}

__device__ __forceinline__ void cp16(uint32_t saddr, const void* gaddr) {
    asm volatile("cp.async.cg.shared.global [%0], [%1], 16;\n" :: "r"(saddr), "l"(gaddr));
}
__device__ __forceinline__ void cp_commit() { asm volatile("cp.async.commit_group;\n"); }
template<int N> __device__ __forceinline__ void cp_wait() {
    asm volatile("cp.async.wait_group %0;\n" :: "n"(N));
}

// ============================================================
// Build fused weight matrix g_W (KPAD x NDIM, row-major), zero pad rows
// ============================================================
__global__ void build_w(const float* __restrict__ W_a1,
                        const float* __restrict__ W_o1,
                        const float* __restrict__ W_ih) {
    int idx = blockIdx.x * 256 + threadIdx.x;
    if (idx >= KPAD * NDIM) return;
    int k = idx / NDIM, c = idx % NDIM;
    float v;
    if (k >= KDIM) {
        v = 0.f;
    } else if (c < 128) {
        v = (k < 33) ? 0.f : W_a1[c * 730 + 10 + (k - 33)];
    } else if (c < 256) {
        int co = c - 128;
        if (k < 32)       v = W_o1[co * 763 + k];
        else if (k == 32) v = W_o1[co * 763 + 42];
        else              v = W_o1[co * 763 + 43 + (k - 33)];
    } else {
        v = W_ih[(c - 256) * 753 + k];
    }
    g_W[idx] = v;
}

// ============================================================
// Per-batch demo precompute
// ============================================================
__global__ void demo_k(const float* __restrict__ x_demo,
                       const float* __restrict__ W_stat, const float* __restrict__ b_stat,
                       const float* __restrict__ W_a1,   const float* __restrict__ b_a1,
                       const float* __restrict__ W_o1,   const float* __restrict__ b_o1) {
    int b = blockIdx.x;
    int tid = threadIdx.x;
    __shared__ float d_sh[10];
    if (tid < 10) {
        float s = b_stat[tid];
        #pragma unroll
        for (int q = 0; q < 10; q++) s += x_demo[b * 10 + q] * W_stat[tid * 10 + q];
        d_sh[tid] = s;
    }
    __syncthreads();
    float sa = b_a1[tid], so = b_o1[tid];
    #pragma unroll
    for (int s = 0; s < 10; s++) {
        sa += d_sh[s] * W_a1[tid * 730 + s];
        so += d_sh[s] * W_o1[tid * 763 + 32 + s];
    }
    g_da[b * HID_ + tid] = sa;
    g_do[b * HID_ + tid] = so;
}

// ============================================================
// Feature kernel (unchanged)
// ============================================================
__global__ void __launch_bounds__(128) feat_k(
    const float* __restrict__ x, const float* __restrict__ f_treat,
    const float* __restrict__ W_x2emb, const float* __restrict__ b_x2emb,
    const float* __restrict__ W_m1a, const float* __restrict__ b_m1a,
    const float* __restrict__ W_m1b, const float* __restrict__ b_m1b,
    const float* __restrict__ W_m2a, const float* __restrict__ b_m2a,
    const float* __restrict__ W_m2b, const float* __restrict__ b_m2b) {
    int m = blockIdx.x;
    int b = m >> 6, t = m & 63;
    int tid = threadIdx.x;

    __shared__ float h1s[80];
    __shared__ float w1a[32], w1b[64], w2a[128], w2b[64], wx[128];
    __shared__ float bx[32], bw1a[8], bw1b[8], bw2a[8], bw2b[8];

    w2a[tid] = W_m2a[tid];
    wx[tid]  = W_x2emb[tid];
    if (tid < 64) { w1b[tid] = W_m1b[tid]; w2b[tid] = W_m2b[tid]; }
    if (tid < 32) { w1a[tid] = W_m1a[tid]; bx[tid] = b_x2emb[tid]; }
    if (tid < 8)  { bw1a[tid] = b_m1a[tid]; bw1b[tid] = b_m1b[tid];
                    bw2a[tid] = b_m2a[tid]; bw2b[tid] = b_m2b[tid]; }
    __syncthreads();

    const float* xr = x + ((size_t)b * 65 + t) * 44;
    float* Frow = g_F + (size_t)m * KPAD;

    if (tid < 10) {
        float xa[4];
        #pragma unroll
        for (int q = 0; q < 4; q++) xa[q] = xr[tid * 4 + q];
        float l1[8];
        #pragma unroll
        for (int j = 0; j < 8; j++) {
            float s = bw1a[j];
            #pragma unroll
            for (int q = 0; q < 4; q++) s += w1a[j * 4 + q] * xa[q];
            l1[j] = eluf(s);
        }
        #pragma unroll
        for (int j = 0; j < 8; j++) {
            float s = bw1b[j];
            #pragma unroll
            for (int q = 0; q < 8; q++) s += w1b[j * 8 + q] * l1[q];
            h1s[tid * 8 + j] = eluf(s);
        }
    } else if (tid >= 96) {
        int jj = tid - 96;
        float s = bx[jj];
        #pragma unroll
        for (int q = 0; q < 4; q++) s += wx[jj * 4 + q] * xr[40 + q];
        Frow[jj] = s;
    } else if (tid == 95) {
        Frow[32] = f_treat[(size_t)b * 65 + t];
    } else if (tid >= 80 && tid < 95) {
        Frow[KDIM + (tid - 80)] = 0.f;
    }
    __syncthreads();

    if (tid < 90) {
        int e = tid;
        int i = e / 9, r = e % 9;
        int jn = (r < i) ? r : r + 1;
        float f[16];
        #pragma unroll
        for (int q = 0; q < 8; q++) { f[q] = h1s[i * 8 + q]; f[8 + q] = h1s[jn * 8 + q]; }
        float l1[8];
        #pragma unroll
        for (int j = 0; j < 8; j++) {
            float s = bw2a[j];
            #pragma unroll
            for (int q = 0; q < 16; q++) s += w2a[j * 16 + q] * f[q];
            l1[j] = eluf(s);
        }
        #pragma unroll
        for (int j = 0; j < 8; j++) {
            float s = bw2b[j];
            #pragma unroll
            for (int q = 0; q < 8; q++) s += w2b[j * 8 + q] * l1[q];
            Frow[33 + e * 8 + j] = eluf(s);
        }
    }
}

// ============================================================
// 3xTF32 tensor-core GEMM, cp.async 3-stage pipeline, raw-smem +
// register-time hi/lo split.
// g_O (16384 x 640) = g_F (16384 x 768) @ g_W (768 x 640)
// 128 threads (2x2 warps), block tile 128x64, warp tile 64x32, BK=16.
// ============================================================
#define GBM 128
#define GBN 64
#define GBK 16
#define NKT (KPAD / GBK)   // 48
#define STG 3
#define ASTR 20            // A smem row stride (floats): bank-bijective for frag loads
#define BSTR 72            // B smem row stride (floats)

__global__ void __launch_bounds__(128) gemm_tf32() {
    __shared__ float As[STG][GBM][ASTR];
    __shared__ float Bs[STG][GBK][BSTR];

    const int tid  = threadIdx.x;
    const int warp = tid >> 5, lane = tid & 31;
    const int g = lane >> 2, tg = lane & 3;
    const int wm = (warp & 1) * 64;
    const int wn = (warp >> 1) * 32;
    const int bm = blockIdx.y * GBM, bn = blockIdx.x * GBN;

    // cp.async source/dest mapping
    const int am = tid >> 2;            // A: row handled (plus +32 per pass would break; use c)
    const int akc = tid & 3;
    const int bk = tid >> 4;            // B: k row
    const int bn4 = (tid & 15) * 4;

    uint32_t sA = (uint32_t)__cvta_generic_to_shared(&As[0][0][0]);
    uint32_t sB = (uint32_t)__cvta_generic_to_shared(&Bs[0][0][0]);

    float acc[4][4][4];
    #pragma unroll
    for (int i = 0; i < 4; i++)
        #pragma unroll
        for (int j = 0; j < 4; j++)
            #pragma unroll
            for (int q = 0; q < 4; q++) acc[i][j][q] = 0.f;

    auto load_tile = [&](int s, int kt) {
        const int k0 = kt * GBK;
        // A tile: 128 rows x 16 k  (512 float4 chunks, 4 per thread)
        #pragma unroll
        for (int p = 0; p < 4; p++) {
            int m = am + p * 32;
            cp16(sA + (uint32_t)(((s * GBM + m) * ASTR + akc * 4) * 4),
                 g_F + (size_t)(bm + m) * KPAD + k0 + akc * 4);
        }
        // B tile: 16 k x 64 n  (256 float4 chunks, 2 per thread)
        #pragma unroll
        for (int p = 0; p < 2; p++) {
            int k = bk + p * 8;
            cp16(sB + (uint32_t)(((s * GBK + k) * BSTR + bn4) * 4),
                 g_W + (size_t)(k0 + k) * NDIM + bn + bn4);
        }
    };

    load_tile(0, 0); cp_commit();
    load_tile(1, 1); cp_commit();

    for (int kt = 0; kt < NKT; kt++) {
        cp_wait<1>();
        __syncthreads();
        const int s = kt % STG;

        #pragma unroll
        for (int ks = 0; ks < 2; ks++) {
            const int kb = ks * 8;
            uint32_t a_h[4][4], a_l[4][4], b_h[4][2], b_l[4][2];
            #pragma unroll
            for (int mt = 0; mt < 4; mt++) {
                int mr = wm + mt * 16 + g;
                #pragma unroll
                for (int r = 0; r < 4; r++) {
                    float raw = As[s][mr + (r & 1) * 8][kb + tg + (r >> 1) * 4];
                    uint32_t hi = f2tf32(raw);
                    a_h[mt][r] = hi;
                    a_l[mt][r] = f2tf32(raw - __uint_as_float(hi));
                }
            }
            #pragma unroll
            for (int nt = 0; nt < 4; nt++) {
                int nc = wn + nt * 8 + g;
                #pragma unroll
                for (int r = 0; r < 2; r++) {
                    float raw = Bs[s][kb + tg + r * 4][nc];
                    uint32_t hi = f2tf32(raw);
                    b_h[nt][r] = hi;
                    b_l[nt][r] = f2tf32(raw - __uint_as_float(hi));
                }
            }
            #pragma unroll
            for (int mt = 0; mt < 4; mt++)
                #pragma unroll
                for (int nt = 0; nt < 4; nt++) {
                    mma_tf32(acc[mt][nt], a_h[mt], b_h[nt]);
                    mma_tf32(acc[mt][nt], a_h[mt], b_l[nt]);
                    mma_tf32(acc[mt][nt], a_l[mt], b_h[nt]);
                }
        }
        __syncthreads();
        if (kt + 2 < NKT) load_tile((kt + 2) % STG, kt + 2);
        cp_commit();
    }

    #pragma unroll
    for (int mt = 0; mt < 4; mt++) {
        #pragma unroll
        for (int nt = 0; nt < 4; nt++) {
            int row = bm + wm + mt * 16 + g;
            int col = bn + wn + nt * 8 + tg * 2;
            *(float2*)&g_O[(size_t)row * NDIM + col] =
                make_float2(acc[mt][nt][0], acc[mt][nt][1]);
            *(float2*)&g_O[(size_t)(row + 8) * NDIM + col] =
                make_float2(acc[mt][nt][2], acc[mt][nt][3]);
        }
    }
}

// ============================================================
// Head kernel (unchanged)
// ============================================================
__global__ void head_k(const float* __restrict__ W_a2, const float* __restrict__ W_o2,
                       float* __restrict__ out) {
    int m = blockIdx.x * 8 + threadIdx.y;
    int lane = threadIdx.x;
    int b = m >> 6;
    const float* row = g_O + (size_t)m * NDIM;
    float sa = 0.f, so = 0.f;
    #pragma unroll
    for (int q = 0; q < 4; q++) {
        int c = lane * 4 + q;
        float av = row[c] + g_da[b * HID_ + c];
        sa += fmaxf(av, 0.f) * W_a2[c];
        float ov = row[128 + c] + g_do[b * HID_ + c];
        so += fmaxf(ov, 0.f) * W_o2[c];
    }
    #pragma unroll
    for (int off = 16; off; off >>= 1) {
        sa += __shfl_down_sync(0xffffffffu, sa, off);
        so += __shfl_down_sync(0xffffffffu, so, off);
    }
    if (lane == 0) {
        out[(size_t)m * 130 + 0] = sa;
        out[(size_t)m * 130 + 1] = so;
    }
}

// ============================================================
// GRU scan: 1 block per batch sample, 384 threads.
// Matvec with packed fma.rn.f32x2 (Blackwell FFMA2).
// ============================================================
__global__ void __launch_bounds__(384, 1) gru_k(
    const float* __restrict__ h0, const float* __restrict__ W_hh,
    const float* __restrict__ b_hh, const float* __restrict__ b_ih,
    float* __restrict__ out) {
    int b = blockIdx.x;
    int j = threadIdx.x;

    __shared__ float h_sh[128];
    __shared__ float gh_sh[384];
    __shared__ float bih_sh[384];

    unsigned long long w2[64];
    #pragma unroll
    for (int q = 0; q < 64; q++)
        w2[q] = ((const unsigned long long*)(W_hh + (size_t)j * 128))[q];
    float bh = b_hh[j];
    bih_sh[j] = b_ih[j];
    if (j < 128) h_sh[j] = h0[b * 128 + j];
    __syncthreads();

    const unsigned long long* h2p = (const unsigned long long*)h_sh;

    for (int t = 0; t < T_; t++) {
        int m = b * T_ + t;
        unsigned long long acc2 = 0ull;  // packed (0.f, 0.f)
        #pragma unroll
        for (int q = 0; q < 64; q++) {
            asm("fma.rn.f32x2 %0, %1, %2, %0;"
                : "+l"(acc2) : "l"(w2[q]), "l"(h2p[q]));
        }
        uint32_t alo, ahi;
        asm("mov.b64 {%0,%1}, %2;" : "=r"(alo), "=r"(ahi) : "l"(acc2));
        gh_sh[j] = bh + __uint_as_float(alo) + __uint_as_float(ahi);
        __syncthreads();
        if (j < 128) {
            const float* gim = g_O + (size_t)m * NDIM + 256;
            float i_r = gim[j]       + bih_sh[j];
            float i_z = gim[128 + j] + bih_sh[128 + j];
            float i_n = gim[256 + j] + bih_sh[256 + j];
            float hr = gh_sh[j], hz = gh_sh[128 + j], hn = gh_sh[256 + j];
            float r = 1.f / (1.f + expf(-(i_r + hr)));
            float z = 1.f / (1.f + expf(-(i_z + hz)));
            float n = tanhf(i_n + r * hn);
            float h_new = (1.f - z) * n + z * h_sh[j];
            h_sh[j] = h_new;
            out[(size_t)m * 130 + 2 + j] = h_new;
        }
        __syncthreads();
    }
}

// ============================================================
extern "C" void kernel_launch(void* const* d_in, const int* in_sizes, int n_in,
                              void* d_out, int out_size) {
    const float* x        = (const float*)d_in[0];
    const float* x_demo   = (const float*)d_in[1];
    const float* f_treat  = (const float*)d_in[2];
    const float* h0       = (const float*)d_in[3];
    const float* W_x2emb  = (const float*)d_in[4];
    const float* b_x2emb  = (const float*)d_in[5];
    const float* W_stat   = (const float*)d_in[6];
    const float* b_stat   = (const float*)d_in[7];
    const float* W_m1a    = (const float*)d_in[8];
    const float* b_m1a    = (const float*)d_in[9];
    const float* W_m1b    = (const float*)d_in[10];
    const float* b_m1b    = (const float*)d_in[11];
    const float* W_m2a    = (const float*)d_in[12];
    const float* b_m2a    = (const float*)d_in[13];
    const float* W_m2b    = (const float*)d_in[14];
    const float* b_m2b    = (const float*)d_in[15];
    const float* W_a1     = (const float*)d_in[16];
    const float* b_a1     = (const float*)d_in[17];
    const float* W_a2     = (const float*)d_in[18];
    const float* W_o1     = (const float*)d_in[19];
    const float* b_o1     = (const float*)d_in[20];
    const float* W_o2     = (const float*)d_in[21];
    const float* W_ih     = (const float*)d_in[22];
    const float* b_ih     = (const float*)d_in[23];
    const float* W_hh     = (const float*)d_in[24];
    const float* b_hh     = (const float*)d_in[25];
    float* out = (float*)d_out;

    build_w<<<(KPAD * NDIM + 255) / 256, 256>>>(W_a1, W_o1, W_ih);
    demo_k<<<B_, 128>>>(x_demo, W_stat, b_stat, W_a1, b_a1, W_o1, b_o1);
    feat_k<<<MROWS, 128>>>(x, f_treat, W_x2emb, b_x2emb,
                           W_m1a, b_m1a, W_m1b, b_m1b,
                           W_m2a, b_m2a, W_m2b, b_m2b);
    dim3 gg(NDIM / GBN, MROWS / GBM);
    gemm_tf32<<<gg, 128>>>();
    head_k<<<MROWS / 8, dim3(32, 8)>>>(W_a2, W_o2, out);
    gru_k<<<B_, 384>>>(h0, W_hh, b_hh, b_ih, out);
}